// round 1
// baseline (speedup 1.0000x reference)
#include <cuda_runtime.h>
#include <math.h>

// Problem constants
#define B 4
#define L 256
#define D 512
#define O 128
#define DP1 513              // D+1 (bias-augmented)
#define BX (B*L)             // 1024 combined (b,x) rows

// Scratch (static device globals; no runtime allocation)
__device__ float g_T[(size_t)BX * O * DP1];   // T[bx][o][j], j contiguous  (~269 MB)
__device__ float g_L1[BX * O];                // w1*(x1@Wlin[:D] + b_lin)
__device__ float g_L2[BX * O];                // w1*(x2@Wlin[D:])

// ---------------------------------------------------------------------------
// Stage 1: T[bx, o, j] = sum_i x1b[bx, i] * W_bil[o, i, j]
// Batched SGEMM: M=1024, N=513, K=513, batch o=128.
// Block tile 64x64, BK=16, 256 threads, 4x4 per thread.
// ---------------------------------------------------------------------------
__global__ __launch_bounds__(256, 2)
void stage1_kernel(const float* __restrict__ x1, const float* __restrict__ Wb)
{
    const int o  = blockIdx.z;
    const int m0 = blockIdx.y * 64;
    const int n0 = blockIdx.x * 64;
    const float* __restrict__ Wo = Wb + (size_t)o * DP1 * DP1;

    __shared__ float As[16][68];   // As[k][m] (transposed)
    __shared__ float Bs[16][68];   // Bs[k][n]

    const int tid = threadIdx.x;
    const int ty = tid >> 4;       // 0..15
    const int tx = tid & 15;       // 0..15

    // A-load mapping: 4 elems per thread, (m = tid/4, k = (tid&3)*4 + i)
    const int a_m = tid >> 2;
    const int a_k = (tid & 3) * 4;
    // B-load mapping: (k = tid/16, n = (tid&15)*4 + i)
    const int b_k = tid >> 4;
    const int b_n = (tid & 15) * 4;

    float acc[4][4] = {};

    for (int k0 = 0; k0 < DP1; k0 += 16) {
        // Load A tile (x1 augmented with ones column at i==512)
        {
            const int mg = m0 + a_m;
            #pragma unroll
            for (int i = 0; i < 4; i++) {
                const int kg = k0 + a_k + i;
                float v;
                if (kg < D)        v = x1[(size_t)mg * D + kg];
                else if (kg == D)  v = 1.0f;
                else               v = 0.0f;
                As[a_k + i][a_m] = v;
            }
        }
        // Load B tile from W_bil[o]
        {
            const int kg = k0 + b_k;
            const bool krow = (kg < DP1);
            #pragma unroll
            for (int i = 0; i < 4; i++) {
                const int ng = n0 + b_n + i;
                float v = 0.0f;
                if (krow && ng < DP1) v = Wo[(size_t)kg * DP1 + ng];
                Bs[b_k][b_n + i] = v;
            }
        }
        __syncthreads();

        #pragma unroll
        for (int k = 0; k < 16; k++) {
            float ra[4], rb[4];
            #pragma unroll
            for (int i = 0; i < 4; i++) ra[i] = As[k][ty * 4 + i];
            #pragma unroll
            for (int j = 0; j < 4; j++) rb[j] = Bs[k][tx * 4 + j];
            #pragma unroll
            for (int i = 0; i < 4; i++)
                #pragma unroll
                for (int j = 0; j < 4; j++)
                    acc[i][j] = fmaf(ra[i], rb[j], acc[i][j]);
        }
        __syncthreads();
    }

    // Epilogue: write T[m][o][n]
    #pragma unroll
    for (int i = 0; i < 4; i++) {
        const int m = m0 + ty * 4 + i;
        float* Trow = g_T + ((size_t)m * O + o) * DP1;
        #pragma unroll
        for (int j = 0; j < 4; j++) {
            const int n = n0 + tx * 4 + j;
            if (n < DP1) Trow[n] = acc[i][j];
        }
    }
}

// ---------------------------------------------------------------------------
// Linear part: L1[m,o] = w1*(x1[m]@Wlin[:D,o] + b_lin[o]); L2[m,o] = w1*(x2[m]@Wlin[D:,o])
// One block per (which, m), 128 threads (one per o).
// ---------------------------------------------------------------------------
__global__ __launch_bounds__(128)
void lin_kernel(const float* __restrict__ x1, const float* __restrict__ x2,
                const float* __restrict__ Wlin, const float* __restrict__ b_lin,
                const float* __restrict__ bw)
{
    const int idx   = blockIdx.x;
    const int which = idx >> 10;       // 0 -> L1, 1 -> L2
    const int m     = idx & 1023;
    const int o     = threadIdx.x;

    const float* xr = (which ? x2 : x1) + (size_t)m * D;
    const float* Wp = Wlin + (which ? (size_t)D * O : 0);

    __shared__ float xs[D];
    for (int d = o; d < D; d += O) xs[d] = xr[d];
    __syncthreads();

    float acc = 0.0f;
    #pragma unroll 8
    for (int d = 0; d < D; d++)
        acc = fmaf(xs[d], Wp[(size_t)d * O + o], acc);

    const float e0 = expf(bw[0]), e1 = expf(bw[1]);
    const float w1 = e1 / (e0 + e1);

    if (which) g_L2[m * O + o] = w1 * acc;
    else       g_L1[m * O + o] = w1 * (acc + b_lin[o]);
}

// ---------------------------------------------------------------------------
// Stage 2: out[bx, y, o] = w0 * sum_j T[bx,o,j]*x2b[b,y,j] + L1[bx,o] + L2[b*L+y,o]
// Per-bx GEMM: M=256 (y), N=128 (o), K=513. Block tile 64x64, BK=16.
// Grid: (o_tiles=2, y_tiles=4, bx=1024)
// ---------------------------------------------------------------------------
__global__ __launch_bounds__(256, 2)
void stage2_kernel(const float* __restrict__ x2, const float* __restrict__ bw,
                   float* __restrict__ out)
{
    const int bx = blockIdx.z;
    const int b  = bx >> 8;
    const int y0 = blockIdx.y * 64;
    const int o0 = blockIdx.x * 64;

    const float* __restrict__ Tb = g_T + (size_t)bx * O * DP1;

    __shared__ float As[16][68];   // As[j][y]
    __shared__ float Bs[16][68];   // Bs[j][o]

    const int tid = threadIdx.x;
    const int ty = tid >> 4;
    const int tx = tid & 15;

    const int a_m = tid >> 2;          // y within tile
    const int a_k = (tid & 3) * 4;
    const int b_o = tid >> 2;          // o within tile
    const int b_j = (tid & 3) * 4;

    float acc[4][4] = {};

    for (int k0 = 0; k0 < DP1; k0 += 16) {
        // Load A = x2b[b, y, j] (ones at j==512)
        {
            const int yg = y0 + a_m;
            const size_t base = ((size_t)b * L + yg) * D;
            #pragma unroll
            for (int i = 0; i < 4; i++) {
                const int jg = k0 + a_k + i;
                float v;
                if (jg < D)        v = x2[base + jg];
                else if (jg == D)  v = 1.0f;
                else               v = 0.0f;
                As[a_k + i][a_m] = v;
            }
        }
        // Load B = T[bx, o, j] (transpose into Bs[j][o])
        {
            const int og = o0 + b_o;
            const float* Tro = Tb + (size_t)og * DP1;
            #pragma unroll
            for (int i = 0; i < 4; i++) {
                const int jg = k0 + b_j + i;
                float v = (jg < DP1) ? Tro[jg] : 0.0f;
                Bs[b_j + i][b_o] = v;
            }
        }
        __syncthreads();

        #pragma unroll
        for (int k = 0; k < 16; k++) {
            float ra[4], rb[4];
            #pragma unroll
            for (int i = 0; i < 4; i++) ra[i] = As[k][ty * 4 + i];
            #pragma unroll
            for (int j = 0; j < 4; j++) rb[j] = Bs[k][tx * 4 + j];
            #pragma unroll
            for (int i = 0; i < 4; i++)
                #pragma unroll
                for (int j = 0; j < 4; j++)
                    acc[i][j] = fmaf(ra[i], rb[j], acc[i][j]);
        }
        __syncthreads();
    }

    const float e0 = expf(bw[0]), e1 = expf(bw[1]);
    const float w0 = e0 / (e0 + e1);

    // Epilogue: out[bx, y, o] contiguous in o — vectorized 4-wide writes
    #pragma unroll
    for (int i = 0; i < 4; i++) {
        const int y = y0 + ty * 4 + i;
        const int yg = b * L + y;
        float4 r;
        const int oc = o0 + tx * 4;
        r.x = w0 * acc[i][0] + g_L1[bx * O + oc + 0] + g_L2[yg * O + oc + 0];
        r.y = w0 * acc[i][1] + g_L1[bx * O + oc + 1] + g_L2[yg * O + oc + 1];
        r.z = w0 * acc[i][2] + g_L1[bx * O + oc + 2] + g_L2[yg * O + oc + 2];
        r.w = w0 * acc[i][3] + g_L1[bx * O + oc + 3] + g_L2[yg * O + oc + 3];
        *reinterpret_cast<float4*>(out + ((size_t)bx * L + y) * O + oc) = r;
    }
}

// ---------------------------------------------------------------------------
extern "C" void kernel_launch(void* const* d_in, const int* in_sizes, int n_in,
                              void* d_out, int out_size)
{
    const float* x1    = (const float*)d_in[0];
    const float* x2    = (const float*)d_in[1];
    const float* bw    = (const float*)d_in[2];
    const float* W_bil = (const float*)d_in[3];
    const float* W_lin = (const float*)d_in[4];
    const float* b_lin = (const float*)d_in[5];
    float* out = (float*)d_out;

    // Stage 1: T = x1b @ W_bil   (grid: 9 n-tiles x 16 m-tiles x 128 o)
    stage1_kernel<<<dim3(9, 16, O), 256>>>(x1, W_bil);

    // Linear precompute (2048 blocks: 1024 for L1, 1024 for L2)
    lin_kernel<<<2048, 128>>>(x1, x2, W_lin, b_lin, bw);

    // Stage 2: out = w0 * (T @ x2b^T) + linear   (grid: 2 o-tiles x 4 y-tiles x 1024 bx)
    stage2_kernel<<<dim3(2, 4, BX), 256>>>(x2, bw, out);
}